// round 16
// baseline (speedup 1.0000x reference)
#include <cuda_runtime.h>
#include <cuda_fp16.h>
#include <math.h>

#define BB 2
#define LL 2048
#define SS 2048
#define HH 16
#define EE 64
#define TQ 64
#define TK 64

#define NELEM (BB * HH * LL * EE)

__device__ __align__(16) __half gK[NELEM];
__device__ __align__(16) __half gV[NELEM];

// ---------------- helpers ----------------
__device__ __forceinline__ unsigned smem_u32(const void* p) {
    unsigned a;
    asm("{ .reg .u64 t; cvta.to.shared.u64 t, %1; cvt.u32.u64 %0, t; }"
        : "=r"(a) : "l"(p));
    return a;
}
#define CP16(dst, src) \
    asm volatile("cp.async.cg.shared.global [%0], [%1], 16;" :: "r"(dst), "l"(src))
#define CP_COMMIT() asm volatile("cp.async.commit_group;" ::: "memory")
#define CP_WAIT0()  asm volatile("cp.async.wait_group 0;" ::: "memory")
#define CP_WAIT1()  asm volatile("cp.async.wait_group 1;" ::: "memory")

__device__ __forceinline__ void ldsm4(unsigned r[4], unsigned addr) {
    asm volatile("ldmatrix.sync.aligned.m8n8.x4.shared.b16 {%0,%1,%2,%3}, [%4];"
                 : "=r"(r[0]), "=r"(r[1]), "=r"(r[2]), "=r"(r[3]) : "r"(addr));
}
__device__ __forceinline__ void ldsm4t(unsigned r[4], unsigned addr) {
    asm volatile("ldmatrix.sync.aligned.m8n8.x4.trans.shared.b16 {%0,%1,%2,%3}, [%4];"
                 : "=r"(r[0]), "=r"(r[1]), "=r"(r[2]), "=r"(r[3]) : "r"(addr));
}
__device__ __forceinline__ void mma16816(float* c, const unsigned a[4],
                                         unsigned b0, unsigned b1) {
    asm volatile(
        "mma.sync.aligned.m16n8k16.row.col.f32.f16.f16.f32 "
        "{%0,%1,%2,%3}, {%4,%5,%6,%7}, {%8,%9}, {%0,%1,%2,%3};"
        : "+f"(c[0]), "+f"(c[1]), "+f"(c[2]), "+f"(c[3])
        : "r"(a[0]), "r"(a[1]), "r"(a[2]), "r"(a[3]), "r"(b0), "r"(b1));
}
__device__ __forceinline__ unsigned pack2h(float lo, float hi) {
    __half2 p = __floats2half2_rn(lo, hi);
    return *reinterpret_cast<unsigned*>(&p);
}
__device__ __forceinline__ float ex2(float x) {
    float r;
    asm("ex2.approx.ftz.f32 %0, %1;" : "=f"(r) : "f"(x));
    return r;
}
__device__ __forceinline__ float lg2(float x) {
    float r;
    asm("lg2.approx.ftz.f32 %0, %1;" : "=f"(r) : "f"(x));
    return r;
}

// ---------------------------------------------------------------------------
// Prep: fp32 [b,s,h,e] -> fp16 [b,h,s,e] for K and V only (Q inlined in attn).
// ---------------------------------------------------------------------------
__global__ __launch_bounds__(256)
void prep(const float* __restrict__ K, const float* __restrict__ V) {
    const unsigned per = NELEM / 4;
    unsigned idx = blockIdx.x * 256u + threadIdx.x;
    if (idx >= 2u * per) return;
    const int t = idx / per;
    const unsigned c = idx % per;

    const unsigned e4 = c & 15;
    const unsigned r  = c >> 4;
    const unsigned h  = r & (HH - 1);
    const unsigned bs = r >> 4;
    const unsigned s  = bs & (LL - 1);
    const unsigned b  = bs >> 11;

    const float* src = (t == 0) ? K : V;
    float4 v = *(const float4*)(src + (size_t)c * 4);
    __half* oh = (t == 0) ? gK : gV;
    const size_t o = (((size_t)(b * HH + h) * LL + s) * EE) + e4 * 4;
    *(uint2*)(oh + o) = make_uint2(pack2h(v.x, v.y), pack2h(v.z, v.w));
}

// ---------------------------------------------------------------------------
// Fused attention. TQ=64, 4 warps, 4 CTAs/SM. 128B-pitch XOR-swizzled smem.
// Q converted fp32->fp16 inline; Q frags persistent across BOTH sweeps.
// Sweep 1: row sums, 128-row K tiles, ring-3 (distance 2).
// Sweep 2: ring-3 (K,V) pairs (distance 2); column-split (2x32) epilogue;
//          normalize via exp2(s - lg2(rsum)).
// ---------------------------------------------------------------------------
__global__ __launch_bounds__(128, 4)
void attn_tc(const float* __restrict__ Qf,
             float* __restrict__ Aout, float* __restrict__ Vout) {
    extern __shared__ char sm[];
    const unsigned uS = smem_u32(sm);
    const unsigned uQ = uS;                               // 64 x 128 = 8192
#define BIG(i)  (uS + 8192u + (unsigned)(i) * 16384u)     // 3 x 16384 (sweep 1)
#define KS2(i)  (uS + 8192u + (unsigned)(i) * 8192u)      // slots 0..2 (sweep 2 K)
#define VS2(i)  (uS + 32768u + (unsigned)(i) * 8192u)     // slots 3..5 (sweep 2 V)

    const int tid  = threadIdx.x;
    const int lane = tid & 31;
    const int w    = tid >> 5;        // 0..3
    const int g    = lane >> 2;
    const int tig  = lane & 3;

    const int bh = blockIdx.y;
    const int b  = bh / HH, h = bh % HH;
    const int qt = (int)gridDim.x - 1 - (int)blockIdx.x;  // heavy tiles first
    const int q0 = qt * TQ;

    const size_t kvbase = (size_t)bh * LL * EE;
    const int nkt  = qt + 1;           // 64-wide tiles (sweep 2)
    const int nbig = (qt + 2) >> 1;    // 128-wide tiles (sweep 1)

    // per-thread store swizzle for cp.async tiles
    const unsigned st_sw = ((((unsigned)tid >> 3) & 7u) << 4);
    const unsigned st_ch = ((unsigned)tid & 7u) * 16u;
    const unsigned st_co = st_ch ^ st_sw;

    // ---- issue big K tiles 0,1 ----
    for (int p = 0; p < 2; ++p) {
        if (p < nbig) {
            const size_t rb = kvbase + (size_t)p * 128 * EE;
            for (int c = tid; c < 1024; c += 128) {
                const int i = c >> 3;
                CP16(BIG(p) + i * 128 + st_co, gK + rb + (size_t)i * EE + (st_ch >> 1));
            }
        }
        CP_COMMIT();
    }

    // ---- inline Q convert: fp32 [b,s,h,e] -> fp16 swizzled smem ----
    {
        const float sc = 0.18033688011112042f;  // 0.125 * log2(e)
        const size_t qf32 = ((size_t)(b * LL + q0) * HH + h) * EE;
        for (int c = tid; c < 1024; c += 128) {
            const int i = c >> 4, ch8 = c & 15;
            float4 qv = *(const float4*)(Qf + qf32 + (size_t)i * HH * EE + ch8 * 4);
            const unsigned off = (unsigned)(i * 128 + ((ch8 * 8) ^ ((i & 7) << 4)));
            *(uint2*)(sm + off) = make_uint2(pack2h(qv.x * sc, qv.y * sc),
                                             pack2h(qv.z * sc, qv.w * sc));
        }
    }

    const int lr  = (lane & 7) + ((lane >> 3) & 1) * 8;
    const int lco = (lane >> 4) * 8;
    const unsigned rd_sw = (((unsigned)lr & 7u) << 4);
    unsigned colq[4];
#pragma unroll
    for (int ks = 0; ks < 4; ++ks) colq[ks] = ((unsigned)(lco * 2 + ks * 32)) ^ rd_sw;
    const unsigned qrowb = (unsigned)((w * 16 + lr) * 128);
    const unsigned krowb = (unsigned)(lr * 128);

    const int gi0 = q0 + w * 16 + g;
    const int gi1 = gi0 + 8;

    float rsum0 = 0.0f, rsum1 = 0.0f;
    unsigned qp[4][4];  // persistent Q frags (both sweeps)

    // ============ sweep 1: row sums, 128-row K tiles, ring-3 ============
    for (int bt = 0; bt < nbig; ++bt) {
        CP_WAIT1();
        __syncthreads();
        if (bt == 0) {
#pragma unroll
            for (int ks = 0; ks < 4; ++ks) ldsm4(qp[ks], uQ + qrowb + colq[ks]);
        }
        if (bt + 2 < nbig) {
            const size_t rb = kvbase + (size_t)(bt + 2) * 128 * EE;
            const unsigned uN = BIG((bt + 2) % 3);
            for (int c = tid; c < 1024; c += 128) {
                const int i = c >> 3;
                CP16(uN + i * 128 + st_co, gK + rb + (size_t)i * EE + (st_ch >> 1));
            }
        }
        CP_COMMIT();
        const unsigned uKbig = BIG(bt % 3);

#pragma unroll
        for (int half = 0; half < 2; ++half) {
            const int k0 = bt * 128 + half * 64;
            if (k0 > q0 + TQ - 1) break;
            const unsigned uK = uKbig + (unsigned)half * 64u * 128u;

            float s[8][4];
#pragma unroll
            for (int nb = 0; nb < 8; ++nb)
#pragma unroll
                for (int c = 0; c < 4; ++c) s[nb][c] = 0.0f;
#pragma unroll
            for (int ks = 0; ks < 4; ++ks) {
#pragma unroll
                for (int jg = 0; jg < 4; ++jg) {
                    unsigned kf[4];
                    ldsm4(kf, uK + jg * 16 * 128 + krowb + colq[ks]);
                    mma16816(s[2 * jg],     qp[ks], kf[0], kf[2]);
                    mma16816(s[2 * jg + 1], qp[ks], kf[1], kf[3]);
                }
            }
            const bool anymask = (k0 + TK > gi0);
#pragma unroll
            for (int nb = 0; nb < 8; ++nb) {
                const int cj = k0 + nb * 8 + 2 * tig;
                float e0 = ex2(s[nb][0]);
                float e1 = ex2(s[nb][1]);
                float e2 = ex2(s[nb][2]);
                float e3 = ex2(s[nb][3]);
                if (anymask) {
                    if (cj     > gi0) e0 = 0.0f;
                    if (cj + 1 > gi0) e1 = 0.0f;
                    if (cj     > gi1) e2 = 0.0f;
                    if (cj + 1 > gi1) e3 = 0.0f;
                }
                rsum0 += e0 + e1;
                rsum1 += e2 + e3;
            }
        }
    }

    rsum0 += __shfl_xor_sync(0xffffffffu, rsum0, 1);
    rsum0 += __shfl_xor_sync(0xffffffffu, rsum0, 2);
    rsum1 += __shfl_xor_sync(0xffffffffu, rsum1, 1);
    rsum1 += __shfl_xor_sync(0xffffffffu, rsum1, 2);
    const float lsub0 = lg2(rsum0);   // e_norm = 2^(s - lsub)
    const float lsub1 = lg2(rsum1);

    // ---- drain, then pre-issue (K,V) pairs 0 and 1 for sweep 2 ----
    CP_WAIT0();
    __syncthreads();
    for (int p = 0; p < 2; ++p) {
        if (p < nkt) {
            const size_t rb = kvbase + (size_t)p * TK * EE;
            for (int c = tid; c < 1024; c += 128) {
                const int arr = c >> 9, i = (c >> 3) & 63;
                const __half* gsrc = arr ? gV : gK;
                const unsigned dst = arr ? VS2(p) : KS2(p);
                CP16(dst + i * 128 + st_co, gsrc + rb + (size_t)i * EE + (st_ch >> 1));
            }
        }
        CP_COMMIT();
    }

    if (Aout) {  // zero the strictly-upper rectangle of this q-strip
        const int c0 = q0 + TQ;
        const int w4 = (SS - c0) >> 2;
        if (w4 > 0) {
            const float4 z = make_float4(0.f, 0.f, 0.f, 0.f);
            float* Abase = Aout + ((size_t)bh * LL + q0) * SS + c0;
            for (int i = tid; i < TQ * w4; i += 128) {
                const int r = i / w4;
                const int c = i - r * w4;
                __stcs((float4*)(Abase + (size_t)r * SS + 4 * c), z);
            }
        }
    }

    float o[8][4];
#pragma unroll
    for (int nb = 0; nb < 8; ++nb)
#pragma unroll
        for (int c = 0; c < 4; ++c) o[nb][c] = 0.0f;

    // ====== sweep 2: normalized A + O (ring-3, distance 2, col-split) ======
    for (int kt = 0; kt < nkt; ++kt) {
        const int k0 = kt * TK;
        CP_WAIT1();
        __syncthreads();
        if (kt + 2 < nkt) {
            const int sl = (kt + 2) % 3;
            const size_t rb = kvbase + (size_t)(kt + 2) * TK * EE;
            for (int c = tid; c < 1024; c += 128) {
                const int arr = c >> 9, i = (c >> 3) & 63;
                const __half* gsrc = arr ? gV : gK;
                const unsigned dst = arr ? VS2(sl) : KS2(sl);
                CP16(dst + i * 128 + st_co, gsrc + rb + (size_t)i * EE + (st_ch >> 1));
            }
        }
        CP_COMMIT();
        const unsigned uK = KS2(kt % 3);
        const unsigned uV = VS2(kt % 3);

        float* A0 = Aout ? (Aout + ((size_t)bh * LL + gi0) * SS + k0) : (float*)0;
        float* A1 = Aout ? (Aout + ((size_t)bh * LL + gi1) * SS + k0) : (float*)0;

#pragma unroll
        for (int cs = 0; cs < 2; ++cs) {   // column half: cols cs*32 .. cs*32+31
            float s[4][4];
#pragma unroll
            for (int nb = 0; nb < 4; ++nb)
#pragma unroll
                for (int c = 0; c < 4; ++c) s[nb][c] = 0.0f;
#pragma unroll
            for (int ks = 0; ks < 4; ++ks) {
#pragma unroll
                for (int jg = 0; jg < 2; ++jg) {
                    unsigned kf[4];
                    ldsm4(kf, uK + (cs * 32 + jg * 16) * 128 + krowb + colq[ks]);
                    mma16816(s[2 * jg],     qp[ks], kf[0], kf[2]);
                    mma16816(s[2 * jg + 1], qp[ks], kf[1], kf[3]);
                }
            }

            const bool anymask = (k0 + cs * 32 + 32 > gi0);
#pragma unroll
            for (int ks2 = 0; ks2 < 2; ++ks2) {
                unsigned ah[4];
#pragma unroll
                for (int half = 0; half < 2; ++half) {
                    const int nb = 2 * ks2 + half;
                    const int cloc = cs * 32 + nb * 8 + 2 * tig;
                    const int cj = k0 + cloc;
                    float e0 = ex2(s[nb][0] - lsub0);
                    float e1 = ex2(s[nb][1] - lsub0);
                    float e2 = ex2(s[nb][2] - lsub1);
                    float e3 = ex2(s[nb][3] - lsub1);
                    if (anymask) {
                        if (cj     > gi0) e0 = 0.0f;
                        if (cj + 1 > gi0) e1 = 0.0f;
                        if (cj     > gi1) e2 = 0.0f;
                        if (cj + 1 > gi1) e3 = 0.0f;
                    }
                    if (A0) {
                        __stcs((float2*)(A0 + cloc), make_float2(e0, e1));
                        __stcs((float2*)(A1 + cloc), make_float2(e2, e3));
                    }
                    ah[2 * half]     = pack2h(e0, e1);
                    ah[2 * half + 1] = pack2h(e2, e3);
                }
#pragma unroll
                for (int dg = 0; dg < 4; ++dg) {
                    unsigned vf[4];
                    ldsm4t(vf, uV + (cs * 32 + ks2 * 16) * 128 + krowb +
                               (((unsigned)(lco * 2 + dg * 32)) ^ rd_sw));
                    mma16816(o[2 * dg],     ah, vf[0], vf[1]);
                    mma16816(o[2 * dg + 1], ah, vf[2], vf[3]);
                }
            }
        }
    }

    if (Vout) {
        float* O0 = Vout + (((size_t)(b * LL + gi0) * HH + h) * EE);
        float* O1 = Vout + (((size_t)(b * LL + gi1) * HH + h) * EE);
#pragma unroll
        for (int nb = 0; nb < 8; ++nb) {
            *(float2*)(O0 + nb * 8 + 2 * tig) = make_float2(o[nb][0], o[nb][1]);
            *(float2*)(O1 + nb * 8 + 2 * tig) = make_float2(o[nb][2], o[nb][3]);
        }
    }
#undef BIG
#undef KS2
#undef VS2
}

// ---------------------------------------------------------------------------
extern "C" void kernel_launch(void* const* d_in, const int* in_sizes, int n_in,
                              void* d_out, int out_size) {
    const float* Q = (const float*)d_in[0];
    const float* K = (const float*)d_in[1];
    const float* V = (const float*)d_in[2];

    const int V_SIZE = BB * LL * HH * EE;
    const int A_SIZE = (int)((size_t)BB * HH * LL * SS);

    float* out  = (float*)d_out;
    float* Vout = 0;
    float* Aout = 0;
    if (out_size >= V_SIZE + A_SIZE) { Vout = out; Aout = out + V_SIZE; }
    else if (out_size == A_SIZE)     { Aout = out; }
    else                             { Vout = out; }

    const unsigned prep_total = 2u * (NELEM / 4);
    prep<<<(prep_total + 255u) / 256u, 256>>>(K, V);

    const int smem = 57344;
    cudaFuncSetAttribute(attn_tc, cudaFuncAttributeMaxDynamicSharedMemorySize, smem);
    dim3 grid1(LL / TQ, BB * HH);
    attn_tc<<<grid1, 128, smem>>>(Q, Aout, Vout);
}